// round 3
// baseline (speedup 1.0000x reference)
#include <cuda_runtime.h>

typedef unsigned long long u64;

constexpr int N      = 256;   // nA == nB
constexpr int R      = 8;     // batch rows per CTA
constexpr int NCTA   = 128;   // 1024 / 8
constexpr int NT     = 256;   // threads per CTA
constexpr int ITERS  = 51;    // 50 no-grad + 1 differentiable
constexpr int KROWS  = 192;   // K rows resident in smem (warp-aligned)
constexpr int KTAIL  = 64;    // rows 192..255: col-slice in regs / row LDG
constexpr int KPAD   = 260;   // padded row length in floats (1040 B: 16B-aligned, S/16 odd -> conflict-free LDS.128)

constexpr int SMEM_K_FLOATS = KROWS * KPAD;            // 49920
constexpr int OFF_AF        = SMEM_K_FLOATS;           // AFs layout [i][r]  (N x R)
constexpr int OFF_BF        = SMEM_K_FLOATS + N * R;   // BFs layout [r][j]  (R x N)
constexpr int SMEM_BYTES    = (SMEM_K_FLOATS + 2 * N * R) * 4;  // 216064 B <= 227 KB

// ---- packed f32x2 helpers (sm_100+) ----
__device__ __forceinline__ u64 ffma2u(u64 a, u64 b, u64 c) {
    asm("fma.rn.f32x2 %0, %1, %2, %3;" : "=l"(c) : "l"(a), "l"(b), "l"(c));
    return c;
}
__device__ __forceinline__ u64 dup2(float x) {
    u64 r; asm("mov.b64 %0, {%1, %1};" : "=l"(r) : "f"(x)); return r;
}
__device__ __forceinline__ void unpack2(u64 v, float& x, float& y) {
    asm("mov.b64 {%0, %1}, %2;" : "=f"(x), "=f"(y) : "l"(v));
}
__device__ __forceinline__ float hsum2(u64 v) {
    float x, y; unpack2(v, x, y); return x + y;
}

extern __shared__ float smem[];

__global__ __launch_bounds__(NT, 1)
void competitive_layer_kernel(const float* __restrict__ AT,
                              const float* __restrict__ BT,
                              const float* __restrict__ Kg,
                              float* __restrict__ C)
{
    float* Ks  = smem;               // [KROWS][KPAD]
    float* AFs = smem + OFF_AF;      // [N][R]
    float* BFs = smem + OFF_BF;      // [R][N]

    const int t    = threadIdx.x;
    const int row0 = blockIdx.x * R;

    // ---- load K rows [0, KROWS) into smem (float4, padded rows) ----
    {
        const float4* Kg4 = reinterpret_cast<const float4*>(Kg);
        for (int idx = t; idx < KROWS * (N / 4); idx += NT) {
            int r_ = idx >> 6;       // row
            int c4 = idx & 63;       // float4 column
            float4 v = Kg4[r_ * 64 + c4];
            *reinterpret_cast<float4*>(&Ks[r_ * KPAD + c4 * 4]) = v;
        }
    }
    // ---- init BF = BT rows (contiguous copy into BFs[r][j]) ----
    {
        const float4* src = reinterpret_cast<const float4*>(BT + (size_t)row0 * N);
        float4* dst = reinterpret_cast<float4*>(BFs);
        for (int idx = t; idx < R * (N / 4); idx += NT) dst[idx] = src[idx];
    }
    // ---- per-thread AT/BT (thread t owns output index t for all R rows) ----
    float at[R], bt[R];
    #pragma unroll
    for (int r = 0; r < R; r++) {
        at[r] = AT[(size_t)(row0 + r) * N + t];
        bt[r] = BT[(size_t)(row0 + r) * N + t];
    }
    // ---- K tail column in registers: ktail[i2] = K[KROWS+i2][t] (coalesced) ----
    float ktail[KTAIL];
    #pragma unroll
    for (int i2 = 0; i2 < KTAIL; i2++) ktail[i2] = Kg[(size_t)(KROWS + i2) * N + t];

    __syncthreads();

    #pragma unroll 1
    for (int it = 0; it < ITERS; it++) {
        // ================= GEMV1: AF[r][t] = at[r] / (1 + sum_j K[t][j]*BF[r][j])
        u64 acc[R];
        #pragma unroll
        for (int r = 0; r < R; r++) acc[r] = 0ull;   // (0.f, 0.f)

        if (t < KROWS) {
            const float* krow = &Ks[t * KPAD];
            #pragma unroll 4
            for (int j = 0; j < N; j += 4) {
                ulonglong2 k2 = *reinterpret_cast<const ulonglong2*>(&krow[j]); // LDS.128
                #pragma unroll
                for (int r = 0; r < R; r++) {
                    acc[r] = ffma2u(k2.x, *reinterpret_cast<const u64*>(&BFs[r * N + j]),     acc[r]);
                    acc[r] = ffma2u(k2.y, *reinterpret_cast<const u64*>(&BFs[r * N + j + 2]), acc[r]);
                }
            }
        } else {
            // warps 6..7: rows come from L2-resident gmem
            const ulonglong2* krow = reinterpret_cast<const ulonglong2*>(Kg + (size_t)t * N);
            #pragma unroll 8
            for (int j4 = 0; j4 < N / 4; j4++) {
                ulonglong2 k2 = __ldg(&krow[j4]);
                int j = j4 * 4;
                #pragma unroll
                for (int r = 0; r < R; r++) {
                    acc[r] = ffma2u(k2.x, *reinterpret_cast<const u64*>(&BFs[r * N + j]),     acc[r]);
                    acc[r] = ffma2u(k2.y, *reinterpret_cast<const u64*>(&BFs[r * N + j + 2]), acc[r]);
                }
            }
        }
        // write AF (layout [i][r], i = t)
        #pragma unroll
        for (int r = 0; r < R; r++) {
            AFs[t * R + r] = at[r] / (1.0f + hsum2(acc[r]));
        }
        __syncthreads();

        // ================= GEMV2: BF[r][t] = bt[r] / (1 + sum_i K[i][t]*AF[r][i])
        u64 accB[R / 2];
        #pragma unroll
        for (int q = 0; q < R / 2; q++) accB[q] = 0ull;

        #pragma unroll 8
        for (int i = 0; i < KROWS; i++) {
            u64 kk = dup2(Ks[i * KPAD + t]);                       // LDS.32, conflict-free
            const u64* afp = reinterpret_cast<const u64*>(&AFs[i * R]); // broadcast LDS
            accB[0] = ffma2u(kk, afp[0], accB[0]);
            accB[1] = ffma2u(kk, afp[1], accB[1]);
            accB[2] = ffma2u(kk, afp[2], accB[2]);
            accB[3] = ffma2u(kk, afp[3], accB[3]);
        }
        #pragma unroll
        for (int i2 = 0; i2 < KTAIL; i2++) {
            u64 kk = dup2(ktail[i2]);                              // register-resident tail
            const u64* afp = reinterpret_cast<const u64*>(&AFs[(KROWS + i2) * R]);
            accB[0] = ffma2u(kk, afp[0], accB[0]);
            accB[1] = ffma2u(kk, afp[1], accB[1]);
            accB[2] = ffma2u(kk, afp[2], accB[2]);
            accB[3] = ffma2u(kk, afp[3], accB[3]);
        }
        #pragma unroll
        for (int q = 0; q < R / 2; q++) {
            float sx, sy; unpack2(accB[q], sx, sy);
            BFs[(2 * q)     * N + t] = bt[2 * q]     / (1.0f + sx);
            BFs[(2 * q + 1) * N + t] = bt[2 * q + 1] / (1.0f + sy);
        }
        __syncthreads();
    }

    // ================= epilogue: C[row0+r][i][j] = K[i][j]*AF[i][r]*BF[r][j]
    #pragma unroll 1
    for (int r = 0; r < R; r++) {
        float* Crow = C + (size_t)(row0 + r) * N * N;
        for (int idx = t; idx < N * (N / 4); idx += NT) {
            int i  = idx >> 6;          // warp-uniform (64 float4s per i-row)
            int j4 = idx & 63;
            float4 k4;
            if (i < KROWS) k4 = *reinterpret_cast<const float4*>(&Ks[i * KPAD + j4 * 4]);
            else           k4 = __ldg(reinterpret_cast<const float4*>(&Kg[(size_t)i * N + j4 * 4]));
            float  a  = AFs[i * R + r];                                     // broadcast
            float4 b4 = *reinterpret_cast<const float4*>(&BFs[r * N + j4 * 4]);
            float4 o;
            o.x = k4.x * a * b4.x;
            o.y = k4.y * a * b4.y;
            o.z = k4.z * a * b4.z;
            o.w = k4.w * a * b4.w;
            *reinterpret_cast<float4*>(&Crow[i * N + j4 * 4]) = o;          // STG.128 coalesced
        }
    }
}

extern "C" void kernel_launch(void* const* d_in, const int* in_sizes, int n_in,
                              void* d_out, int out_size)
{
    const float* AT = (const float*)d_in[0];   // [1024, 256]
    const float* BT = (const float*)d_in[1];   // [1024, 256]
    const float* Kg = (const float*)d_in[2];   // [256, 256]
    float*       C  = (float*)d_out;           // [1024, 256, 256]

    cudaFuncSetAttribute(competitive_layer_kernel,
                         cudaFuncAttributeMaxDynamicSharedMemorySize, SMEM_BYTES);
    competitive_layer_kernel<<<NCTA, NT, SMEM_BYTES>>>(AT, BT, Kg, C);
}